// round 1
// baseline (speedup 1.0000x reference)
#include <cuda_runtime.h>
#include <math.h>

#define NB   16
#define NC   256
#define NH   64
#define NW   64
#define NE   4
#define NTAP 9
#define SEXP (NC*NC*NTAP)   // 589824 weights per expert / per sample

// Scratch (device globals: allocation-free per harness rules)
__device__ float g_pooled[NB*NC];
__device__ float g_routing[NB*NE];
__device__ float g_weff[(size_t)NB*SEXP];   // 37.7 MB per-sample folded weights

// ---------------------------------------------------------------------------
// Kernel 1: global average pool  x[b,c,:,:] -> pooled[b,c]
// ---------------------------------------------------------------------------
__global__ void pool_kernel(const float* __restrict__ x) {
    int bc = blockIdx.x;                       // 0..NB*NC-1
    const float4* p = (const float4*)(x + (size_t)bc * NH * NW);
    float s = 0.f;
    for (int i = threadIdx.x; i < NH*NW/4; i += blockDim.x) {
        float4 v = p[i];
        s += v.x + v.y + v.z + v.w;
    }
    #pragma unroll
    for (int o = 16; o; o >>= 1) s += __shfl_xor_sync(0xffffffffu, s, o);
    __shared__ float red[4];
    if ((threadIdx.x & 31) == 0) red[threadIdx.x >> 5] = s;
    __syncthreads();
    if (threadIdx.x == 0) {
        float t = red[0] + red[1] + red[2] + red[3];
        g_pooled[bc] = t * (1.0f / (NH * NW));
    }
}

// ---------------------------------------------------------------------------
// Kernel 2: routing = sigmoid(pooled @ w_route^T + b_route)   [16,4]
// ---------------------------------------------------------------------------
__global__ void route_kernel(const float* __restrict__ wr, const float* __restrict__ br) {
    int t = threadIdx.x;
    if (t >= NB * NE) return;
    int b = t >> 2, e = t & 3;
    float acc = br[e];
    const float* pw = wr + e * NC;
    const float* pp = g_pooled + b * NC;
    #pragma unroll 8
    for (int c = 0; c < NC; ++c) acc = fmaf(pp[c], pw[c], acc);
    g_routing[t] = 1.f / (1.f + expf(-acc));
}

// ---------------------------------------------------------------------------
// Kernel 3: fold experts  W_eff[b] = sum_e routing[b,e] * W[e]
// ---------------------------------------------------------------------------
__global__ void fold_kernel(const float* __restrict__ we) {
    const int J = SEXP / 4;                    // float4 elements per expert
    int j = blockIdx.x * blockDim.x + threadIdx.x;
    if (j >= J) return;
    float4 w0 = ((const float4*)we)[j];
    float4 w1 = ((const float4*)we)[j + J];
    float4 w2 = ((const float4*)we)[j + 2*J];
    float4 w3 = ((const float4*)we)[j + 3*J];
    #pragma unroll
    for (int b = 0; b < NB; ++b) {
        float r0 = g_routing[b*4+0], r1 = g_routing[b*4+1];
        float r2 = g_routing[b*4+2], r3 = g_routing[b*4+3];
        float4 o;
        o.x = w0.x*r0 + w1.x*r1 + w2.x*r2 + w3.x*r3;
        o.y = w0.y*r0 + w1.y*r1 + w2.y*r2 + w3.y*r3;
        o.z = w0.z*r0 + w1.z*r1 + w2.z*r2 + w3.z*r3;
        o.w = w0.w*r0 + w1.w*r1 + w2.w*r2 + w3.w*r3;
        ((float4*)g_weff)[(size_t)b * J + j] = o;
    }
}

// ---------------------------------------------------------------------------
// Kernel 4: per-sample conv3x3 (pad 1) with folded weights + BN + SiLU.
// Implicit GEMM: M=64 out-channels x N=64 pixels (one image row) per block.
// 128 threads, register tile 4 (ch) x 8 (cols), K chunked by TK=8 in-channels.
// ---------------------------------------------------------------------------
#define TK 8
#define TM 64

__global__ __launch_bounds__(128, 4)
void conv_kernel(const float* __restrict__ x,
                 const float* __restrict__ gamma,
                 const float* __restrict__ beta,
                 const float* __restrict__ mean,
                 const float* __restrict__ var,
                 float* __restrict__ out) {
    // sA[(c*9+t)*65 + o]  : folded weights, padded row (65) -> conflict-free STS
    // sB[c*198 + r*66 + (1+w)] : input rows h-1..h+1, cols -1..64 (zero-padded)
    __shared__ float sA[TK * NTAP * 65];       // 4680 floats
    __shared__ float sB[TK * 3 * 66];          // 1584 floats

    const int ct  = blockIdx.x;                // channel tile 0..3
    const int h   = blockIdx.y;                // output row 0..63
    const int b   = blockIdx.z;                // batch 0..15
    const int tid = threadIdx.x;
    const int om  = tid & 15;                  // o-subtile: o = obase + om*4 + i
    const int cm  = tid >> 4;                  // col group:  w0 = cm*8
    const int obase = ct * TM;
    const int w0 = cm * 8;

    const float* gw = g_weff + (size_t)b * SEXP + (size_t)obase * (NC * NTAP);
    const float* gx = x + (size_t)b * NC * NH * NW;

    float acc[4][8];
    #pragma unroll
    for (int i = 0; i < 4; ++i)
        #pragma unroll
        for (int j = 0; j < 8; ++j) acc[i][j] = 0.f;

    for (int c0 = 0; c0 < NC; c0 += TK) {
        // --- fill sA: TK*9*64 = 4608 weights (coalesced LDG, conflict-free STS)
        for (int lin = tid; lin < TK * NTAP * TM; lin += 128) {
            int o   = lin / (TK * NTAP);
            int idx = lin - o * (TK * NTAP);   // idx = c*9 + t, 0..71
            sA[idx * 65 + o] = gw[(size_t)o * (NC * NTAP) + c0 * NTAP + idx];
        }
        // --- fill sB: TK channels x 3 halo rows x 66 cols (zero padding)
        for (int lin = tid; lin < TK * 3 * 66; lin += 128) {
            int c   = lin / 198;
            int rem = lin - c * 198;
            int r   = rem / 66;
            int j   = rem - r * 66;
            int hin = h + r - 1;
            int w   = j - 1;
            float v = 0.f;
            if ((unsigned)hin < NH && (unsigned)w < NW)
                v = gx[((size_t)(c0 + c) * NH + hin) * NW + w];
            sB[lin] = v;
        }
        __syncthreads();

        #pragma unroll 1
        for (int c = 0; c < TK; ++c) {
            float bv[3][10];
            #pragma unroll
            for (int r = 0; r < 3; ++r)
                #pragma unroll
                for (int j = 0; j < 10; ++j)
                    bv[r][j] = sB[c * 198 + r * 66 + w0 + j];
            #pragma unroll
            for (int t = 0; t < 9; ++t) {
                const int dh = t / 3, dw = t - dh * 3;
                float a0 = sA[(c * 9 + t) * 65 + om * 4 + 0];
                float a1 = sA[(c * 9 + t) * 65 + om * 4 + 1];
                float a2 = sA[(c * 9 + t) * 65 + om * 4 + 2];
                float a3 = sA[(c * 9 + t) * 65 + om * 4 + 3];
                #pragma unroll
                for (int j = 0; j < 8; ++j) {
                    float bb = bv[dh][dw + j];
                    acc[0][j] = fmaf(a0, bb, acc[0][j]);
                    acc[1][j] = fmaf(a1, bb, acc[1][j]);
                    acc[2][j] = fmaf(a2, bb, acc[2][j]);
                    acc[3][j] = fmaf(a3, bb, acc[3][j]);
                }
            }
        }
        __syncthreads();
    }

    // --- epilogue: BN (running stats) + SiLU, vectorized store
    #pragma unroll
    for (int i = 0; i < 4; ++i) {
        int o = obase + om * 4 + i;
        float inv = gamma[o] * rsqrtf(var[o] + 1e-5f);
        float add = beta[o] - mean[o] * inv;
        float* po = out + (((size_t)b * NC + o) * NH + h) * NW + w0;
        float tmp[8];
        #pragma unroll
        for (int j = 0; j < 8; ++j) {
            float z = acc[i][j] * inv + add;
            tmp[j] = z / (1.f + expf(-z));     // SiLU = z * sigmoid(z)
        }
        ((float4*)po)[0] = make_float4(tmp[0], tmp[1], tmp[2], tmp[3]);
        ((float4*)po)[1] = make_float4(tmp[4], tmp[5], tmp[6], tmp[7]);
    }
}

// ---------------------------------------------------------------------------
extern "C" void kernel_launch(void* const* d_in, const int* in_sizes, int n_in,
                              void* d_out, int out_size) {
    const float* x        = (const float*)d_in[0];  // [16,256,64,64]
    const float* w_route  = (const float*)d_in[1];  // [4,256]
    const float* b_route  = (const float*)d_in[2];  // [4]
    const float* w_expert = (const float*)d_in[3];  // [4,256,256,3,3]
    const float* bn_gamma = (const float*)d_in[4];  // [256]
    const float* bn_beta  = (const float*)d_in[5];
    const float* bn_mean  = (const float*)d_in[6];
    const float* bn_var   = (const float*)d_in[7];
    float* out = (float*)d_out;

    pool_kernel<<<NB * NC, 128>>>(x);
    route_kernel<<<1, 64>>>(w_route, b_route);
    fold_kernel<<<(SEXP / 4 + 255) / 256, 256>>>(w_expert);
    dim3 grid(NC / TM, NH, NB);
    conv_kernel<<<grid, 128>>>(x, bn_gamma, bn_beta, bn_mean, bn_var, out);
}